// round 11
// baseline (speedup 1.0000x reference)
#include <cuda_runtime.h>

#define C1 1.125f
#define C2 (-1.0f/24.0f)

__device__ __forceinline__ float4 ld4(const float* p) {
    return *reinterpret_cast<const float4*>(p);
}
__device__ __forceinline__ void st4(float* p, float4 v) {
    *reinterpret_cast<float4*>(p) = v;
}
__device__ __forceinline__ float4 f4zero() { return make_float4(0.f,0.f,0.f,0.f); }

// (C1*(a-b) + C2*(c-d)) * s
__device__ __forceinline__ float4 stencil4(float4 a, float4 b, float4 c, float4 d, float s) {
    float4 r;
    r.x = (C1 * (a.x - b.x) + C2 * (c.x - d.x)) * s;
    r.y = (C1 * (a.y - b.y) + C2 * (c.y - d.y)) * s;
    r.z = (C1 * (a.z - b.z) + C2 * (c.z - d.z)) * s;
    r.w = (C1 * (a.w - b.w) + C2 * (c.w - d.w)) * s;
    return r;
}
// update_E x-stencil: lanewise needs x-2..x+1
__device__ __forceinline__ float4 xderiv_E(float4 c, float4 p, float4 n, float s) {
    float4 r;
    r.x = (C1 * (c.x - p.w) + C2 * (c.y - p.z)) * s;
    r.y = (C1 * (c.y - c.x) + C2 * (c.z - p.w)) * s;
    r.z = (C1 * (c.z - c.y) + C2 * (c.w - c.x)) * s;
    r.w = (C1 * (c.w - c.z) + C2 * (n.x - c.y)) * s;
    return r;
}
// update_H x-stencil: lanewise needs x-1..x+2
__device__ __forceinline__ float4 xderiv_H(float4 c, float4 p, float4 n, float s) {
    float4 r;
    r.x = (C1 * (c.y - c.x) + C2 * (c.z - p.w)) * s;
    r.y = (C1 * (c.z - c.y) + C2 * (c.w - c.x)) * s;
    r.z = (C1 * (c.w - c.z) + C2 * (n.x - c.y)) * s;
    r.w = (C1 * (n.x - c.w) + C2 * (n.y - c.z)) * s;
    return r;
}

#define ROWS 4

// ---------------- Kernel 1: update_E (x4 vector, 4 y-rows/thread) ----------------
__global__ void __launch_bounds__(256) upd_E(
    const float* __restrict__ ca, const float* __restrict__ cb,
    const float* __restrict__ Ey, const float* __restrict__ Hx,
    const float* __restrict__ Hz,
    const float* __restrict__ mHxz, const float* __restrict__ mHzx,
    const float* __restrict__ ky, const float* __restrict__ ay,
    const float* __restrict__ by,
    const float* __restrict__ kx, const float* __restrict__ ax,
    const float* __restrict__ bx,
    const float* __restrict__ prdy, const float* __restrict__ prdx,
    float* __restrict__ outEy, float* __restrict__ outmHxz,
    float* __restrict__ outmHzx,
    int NY, int NX)
{
    int x4 = (blockIdx.x * blockDim.x + threadIdx.x) * 4;
    int y0 = (blockIdx.y * blockDim.y + threadIdx.y) * ROWS;
    int b  = blockIdx.z;
    if (x4 >= NX || y0 >= NY) return;

    const float rdx = *prdx;
    const float rdy = *prdy;

    size_t plane = (size_t)NY * NX;
    size_t base0 = (size_t)b * plane + (size_t)y0 * NX + x4;

    const bool xlo = (x4 >= 4);
    const bool xhi = (x4 + 4 < NX);

    // ---- x-derivative of Hz for each of the 4 rows ----
    float4 dHzdx[ROWS];
    #pragma unroll
    for (int r = 0; r < ROWS; r++) {
        size_t br = base0 + (size_t)r * NX;
        float4 c = ld4(Hz + br);
        float4 p = xlo ? ld4(Hz + br - 4) : f4zero();
        float4 n = xhi ? ld4(Hz + br + 4) : f4zero();
        dHzdx[r] = xderiv_E(c, p, n, rdx);
    }

    // ---- y-derivative of Hx: rows y0-2 .. y0+4 (7 loads for 4 rows) ----
    float4 h[ROWS + 3];
    h[0] = (y0 >= 2) ? ld4(Hx + base0 - 2*(size_t)NX) : f4zero();
    h[1] = (y0 >= 1) ? ld4(Hx + base0 -   (size_t)NX) : f4zero();
    #pragma unroll
    for (int r = 0; r < ROWS; r++)
        h[2 + r] = ld4(Hx + base0 + (size_t)r * NX);
    h[ROWS + 2] = (y0 + ROWS < NY) ? ld4(Hx + base0 + (size_t)ROWS * NX) : f4zero();

    float4 dHxdz[ROWS];
    #pragma unroll
    for (int r = 0; r < ROWS; r++)                  // row y: C1*(h[y]-h[y-1]) + C2*(h[y+1]-h[y-2])
        dHxdz[r] = stencil4(h[r + 2], h[r + 1], h[r + 3], h[r], rdy);

    // ---- x coefficients (shared across rows) ----
    float4 bx4 = ld4(bx + x4);
    float4 ax4 = ld4(ax + x4);
    float4 kx4 = ld4(kx + x4);

    #pragma unroll
    for (int r = 0; r < ROWS; r++) {
        int yr = y0 + r;
        size_t br = base0 + (size_t)r * NX;

        float byv = by[yr], ayv = ay[yr];
        float rky = 1.0f / ky[yr];

        float4 mzx = ld4(mHzx + br);
        mzx.x = bx4.x * mzx.x + ax4.x * dHzdx[r].x;
        mzx.y = bx4.y * mzx.y + ax4.y * dHzdx[r].y;
        mzx.z = bx4.z * mzx.z + ax4.z * dHzdx[r].z;
        mzx.w = bx4.w * mzx.w + ax4.w * dHzdx[r].w;

        float4 mxz = ld4(mHxz + br);
        mxz.x = byv * mxz.x + ayv * dHxdz[r].x;
        mxz.y = byv * mxz.y + ayv * dHxdz[r].y;
        mxz.z = byv * mxz.z + ayv * dHxdz[r].z;
        mxz.w = byv * mxz.w + ayv * dHxdz[r].w;

        size_t cidx = (size_t)yr * NX + x4;
        float4 ca4 = ld4(ca + cidx);
        float4 cb4 = ld4(cb + cidx);
        float4 ey  = ld4(Ey + br);

        ey.x = ca4.x * ey.x + cb4.x * ((dHzdx[r].x / kx4.x + mzx.x) - (dHxdz[r].x * rky + mxz.x));
        ey.y = ca4.y * ey.y + cb4.y * ((dHzdx[r].y / kx4.y + mzx.y) - (dHxdz[r].y * rky + mxz.y));
        ey.z = ca4.z * ey.z + cb4.z * ((dHzdx[r].z / kx4.z + mzx.z) - (dHxdz[r].z * rky + mxz.z));
        ey.w = ca4.w * ey.w + cb4.w * ((dHzdx[r].w / kx4.w + mzx.w) - (dHxdz[r].w * rky + mxz.w));

        st4(outEy   + br, ey);
        st4(outmHzx + br, mzx);
        st4(outmHxz + br, mxz);
    }
}

// ---------------- Kernel 2: update_H (x4 vector, 4 y-rows/thread) ----------------
__global__ void __launch_bounds__(256) upd_H(
    const float* __restrict__ cq,
    const float* __restrict__ EyNew,
    const float* __restrict__ Hx, const float* __restrict__ Hz,
    const float* __restrict__ mEyx, const float* __restrict__ mEyz,
    const float* __restrict__ kyh, const float* __restrict__ ayh,
    const float* __restrict__ byh,
    const float* __restrict__ kxh, const float* __restrict__ axh,
    const float* __restrict__ bxh,
    const float* __restrict__ prdy, const float* __restrict__ prdx,
    float* __restrict__ outHx, float* __restrict__ outHz,
    float* __restrict__ outmEyx, float* __restrict__ outmEyz,
    int NY, int NX)
{
    int x4 = (blockIdx.x * blockDim.x + threadIdx.x) * 4;
    int y0 = (blockIdx.y * blockDim.y + threadIdx.y) * ROWS;
    int b  = blockIdx.z;
    if (x4 >= NX || y0 >= NY) return;

    const float rdx = *prdx;
    const float rdy = *prdy;

    size_t plane = (size_t)NY * NX;
    size_t base0 = (size_t)b * plane + (size_t)y0 * NX + x4;

    const bool xlo = (x4 >= 4);
    const bool xhi = (x4 + 4 < NX);

    // ---- EyNew rows y0-1 .. y0+5 (7 loads; centers e[1..4]) ----
    float4 e[ROWS + 3];
    e[0] = (y0 >= 1) ? ld4(EyNew + base0 - (size_t)NX) : f4zero();
    #pragma unroll
    for (int r = 0; r < ROWS; r++)
        e[1 + r] = ld4(EyNew + base0 + (size_t)r * NX);
    e[ROWS + 1] = (y0 + ROWS     < NY) ? ld4(EyNew + base0 + (size_t)ROWS       * NX) : f4zero();
    e[ROWS + 2] = (y0 + ROWS + 1 < NY) ? ld4(EyNew + base0 + (size_t)(ROWS + 1) * NX) : f4zero();

    // x-derivatives (x-halos per center row)
    float4 dEydx[ROWS];
    #pragma unroll
    for (int r = 0; r < ROWS; r++) {
        size_t br = base0 + (size_t)r * NX;
        float4 p = xlo ? ld4(EyNew + br - 4) : f4zero();
        float4 n = xhi ? ld4(EyNew + br + 4) : f4zero();
        dEydx[r] = xderiv_H(e[1 + r], p, n, rdx);
    }
    // y-derivatives: row y uses y+1, y, y+2, y-1
    float4 dEydz[ROWS];
    #pragma unroll
    for (int r = 0; r < ROWS; r++)
        dEydz[r] = stencil4(e[r + 2], e[r + 1], e[r + 3], e[r], rdy);

    // ---- x coefficients (shared) ----
    float4 bxh4 = ld4(bxh + x4);
    float4 axh4 = ld4(axh + x4);
    float4 kxh4 = ld4(kxh + x4);

    #pragma unroll
    for (int r = 0; r < ROWS; r++) {
        int yr = y0 + r;
        size_t br = base0 + (size_t)r * NX;

        float byhv = byh[yr], ayhv = ayh[yr];
        float rkyh = 1.0f / kyh[yr];

        float4 mez = ld4(mEyz + br);
        mez.x = byhv * mez.x + ayhv * dEydz[r].x;
        mez.y = byhv * mez.y + ayhv * dEydz[r].y;
        mez.z = byhv * mez.z + ayhv * dEydz[r].z;
        mez.w = byhv * mez.w + ayhv * dEydz[r].w;

        float4 mex = ld4(mEyx + br);
        mex.x = bxh4.x * mex.x + axh4.x * dEydx[r].x;
        mex.y = bxh4.y * mex.y + axh4.y * dEydx[r].y;
        mex.z = bxh4.z * mex.z + axh4.z * dEydx[r].z;
        mex.w = bxh4.w * mex.w + axh4.w * dEydx[r].w;

        size_t cidx = (size_t)yr * NX + x4;
        float4 cq4 = ld4(cq + cidx);

        float4 hx = ld4(Hx + br);
        hx.x = hx.x - cq4.x * (dEydz[r].x * rkyh + mez.x);
        hx.y = hx.y - cq4.y * (dEydz[r].y * rkyh + mez.y);
        hx.z = hx.z - cq4.z * (dEydz[r].z * rkyh + mez.z);
        hx.w = hx.w - cq4.w * (dEydz[r].w * rkyh + mez.w);

        float4 hz = ld4(Hz + br);
        hz.x = hz.x + cq4.x * (dEydx[r].x / kxh4.x + mex.x);
        hz.y = hz.y + cq4.y * (dEydx[r].y / kxh4.y + mex.y);
        hz.z = hz.z + cq4.z * (dEydx[r].z / kxh4.z + mex.z);
        hz.w = hz.w + cq4.w * (dEydx[r].w / kxh4.w + mex.w);

        st4(outHx   + br, hx);
        st4(outHz   + br, hz);
        st4(outmEyz + br, mez);
        st4(outmEyx + br, mex);
    }
}

extern "C" void kernel_launch(void* const* d_in, const int* in_sizes, int n_in,
                              void* d_out, int out_size)
{
    const float* ca    = (const float*)d_in[0];
    const float* cb    = (const float*)d_in[1];
    const float* cq    = (const float*)d_in[2];
    const float* Ey    = (const float*)d_in[3];
    const float* Hx    = (const float*)d_in[4];
    const float* Hz    = (const float*)d_in[5];
    const float* mHxz  = (const float*)d_in[6];
    const float* mHzx  = (const float*)d_in[7];
    const float* mEyx  = (const float*)d_in[8];
    const float* mEyz  = (const float*)d_in[9];
    const float* ky    = (const float*)d_in[10];
    const float* kyh   = (const float*)d_in[11];
    const float* ay    = (const float*)d_in[12];
    const float* ayh   = (const float*)d_in[13];
    const float* by    = (const float*)d_in[14];
    const float* byh   = (const float*)d_in[15];
    const float* kx    = (const float*)d_in[16];
    const float* kxh   = (const float*)d_in[17];
    const float* ax    = (const float*)d_in[18];
    const float* axh   = (const float*)d_in[19];
    const float* bx    = (const float*)d_in[20];
    const float* bxh   = (const float*)d_in[21];
    const float* prdy  = (const float*)d_in[22];
    const float* prdx  = (const float*)d_in[23];

    int NY = in_sizes[10];
    int NX = in_sizes[16];
    int B  = in_sizes[3] / (NY * NX);

    size_t plane = (size_t)NY * NX;
    size_t field = (size_t)B * plane;

    float* out = (float*)d_out;
    float* oEy   = out + 0 * field;
    float* oHx   = out + 1 * field;
    float* oHz   = out + 2 * field;
    float* omHxz = out + 3 * field;
    float* omHzx = out + 4 * field;
    float* omEyx = out + 5 * field;
    float* omEyz = out + 6 * field;

    // each thread: 4 x-elements x 4 y-rows
    dim3 block(64, 4, 1);
    int nx4 = NX / 4;                        // 512
    int nyr = (NY + ROWS - 1) / ROWS;        // 512
    dim3 grid((nx4 + 63) / 64, (nyr + 3) / 4, B);

    upd_E<<<grid, block>>>(ca, cb, Ey, Hx, Hz, mHxz, mHzx,
                           ky, ay, by, kx, ax, bx, prdy, prdx,
                           oEy, omHxz, omHzx, NY, NX);

    upd_H<<<grid, block>>>(cq, oEy, Hx, Hz, mEyx, mEyz,
                           kyh, ayh, byh, kxh, axh, bxh, prdy, prdx,
                           oHx, oHz, omEyx, omEyz, NY, NX);
}

// round 12
// speedup vs baseline: 1.0751x; 1.0751x over previous
#include <cuda_runtime.h>

#define C1 1.125f
#define C2 (-1.0f/24.0f)

__device__ __forceinline__ float4 ld4(const float* p) {
    return *reinterpret_cast<const float4*>(p);
}
__device__ __forceinline__ void st4(float* p, float4 v) {
    *reinterpret_cast<float4*>(p) = v;
}
__device__ __forceinline__ float4 f4zero() { return make_float4(0.f,0.f,0.f,0.f); }

// (C1*(a-b) + C2*(c-d)) * s
__device__ __forceinline__ float4 stencil4(float4 a, float4 b, float4 c, float4 d, float s) {
    float4 r;
    r.x = (C1 * (a.x - b.x) + C2 * (c.x - d.x)) * s;
    r.y = (C1 * (a.y - b.y) + C2 * (c.y - d.y)) * s;
    r.z = (C1 * (a.z - b.z) + C2 * (c.z - d.z)) * s;
    r.w = (C1 * (a.w - b.w) + C2 * (c.w - d.w)) * s;
    return r;
}
// update_E x-stencil: lanewise needs x-2..x+1
__device__ __forceinline__ float4 xderiv_E(float4 c, float4 p, float4 n, float s) {
    float4 r;
    r.x = (C1 * (c.x - p.w) + C2 * (c.y - p.z)) * s;
    r.y = (C1 * (c.y - c.x) + C2 * (c.z - p.w)) * s;
    r.z = (C1 * (c.z - c.y) + C2 * (c.w - c.x)) * s;
    r.w = (C1 * (c.w - c.z) + C2 * (n.x - c.y)) * s;
    return r;
}
// update_H x-stencil: lanewise needs x-1..x+2
__device__ __forceinline__ float4 xderiv_H(float4 c, float4 p, float4 n, float s) {
    float4 r;
    r.x = (C1 * (c.y - c.x) + C2 * (c.z - p.w)) * s;
    r.y = (C1 * (c.z - c.y) + C2 * (c.w - c.x)) * s;
    r.z = (C1 * (c.w - c.z) + C2 * (n.x - c.y)) * s;
    r.w = (C1 * (n.x - c.w) + C2 * (n.y - c.z)) * s;
    return r;
}

#define NB 2   // batches per thread (B is 2 for this problem)

// ------------- Kernel 1: update_E (x4 vector, both batches per thread) -------------
__global__ void __launch_bounds__(256) upd_E(
    const float* __restrict__ ca, const float* __restrict__ cb,
    const float* __restrict__ Ey, const float* __restrict__ Hx,
    const float* __restrict__ Hz,
    const float* __restrict__ mHxz, const float* __restrict__ mHzx,
    const float* __restrict__ ky, const float* __restrict__ ay,
    const float* __restrict__ by,
    const float* __restrict__ kx, const float* __restrict__ ax,
    const float* __restrict__ bx,
    const float* __restrict__ prdy, const float* __restrict__ prdx,
    float* __restrict__ outEy, float* __restrict__ outmHxz,
    float* __restrict__ outmHzx,
    int NY, int NX)
{
    int x4 = (blockIdx.x * blockDim.x + threadIdx.x) * 4;
    int y  = blockIdx.y * blockDim.y + threadIdx.y;
    if (x4 >= NX || y >= NY) return;

    const float rdx = *prdx;
    const float rdy = *prdy;

    size_t plane = (size_t)NY * NX;
    size_t cell  = (size_t)y * NX + x4;

    const bool xlo = (x4 >= 4);
    const bool xhi = (x4 + 4 < NX);
    const bool y1  = (y >= 1), y2 = (y >= 2), yp = (y + 1 < NY);

    // ---- coefficients: loaded ONCE, used for both batches ----
    float4 bx4 = ld4(bx + x4);
    float4 ax4 = ld4(ax + x4);
    float4 kx4 = ld4(kx + x4);
    float  byv = by[y], ayv = ay[y];
    float  rky = 1.0f / ky[y];
    float4 ca4 = ld4(ca + cell);
    float4 cb4 = ld4(cb + cell);

    #pragma unroll
    for (int b = 0; b < NB; b++) {
        size_t base = (size_t)b * plane + cell;

        // x-derivative of Hz
        float4 c = ld4(Hz + base);
        float4 p = xlo ? ld4(Hz + base - 4) : f4zero();
        float4 n = xhi ? ld4(Hz + base + 4) : f4zero();
        float4 dHzdx = xderiv_E(c, p, n, rdx);

        // y-derivative of Hx
        float4 r0  = ld4(Hx + base);
        float4 rm1 = y1 ? ld4(Hx + base -   (size_t)NX) : f4zero();
        float4 rm2 = y2 ? ld4(Hx + base - 2*(size_t)NX) : f4zero();
        float4 rp1 = yp ? ld4(Hx + base +   (size_t)NX) : f4zero();
        float4 dHxdz = stencil4(r0, rm1, rp1, rm2, rdy);

        float4 mzx = ld4(mHzx + base);
        mzx.x = bx4.x * mzx.x + ax4.x * dHzdx.x;
        mzx.y = bx4.y * mzx.y + ax4.y * dHzdx.y;
        mzx.z = bx4.z * mzx.z + ax4.z * dHzdx.z;
        mzx.w = bx4.w * mzx.w + ax4.w * dHzdx.w;

        float4 mxz = ld4(mHxz + base);
        mxz.x = byv * mxz.x + ayv * dHxdz.x;
        mxz.y = byv * mxz.y + ayv * dHxdz.y;
        mxz.z = byv * mxz.z + ayv * dHxdz.z;
        mxz.w = byv * mxz.w + ayv * dHxdz.w;

        float4 ey = ld4(Ey + base);
        ey.x = ca4.x * ey.x + cb4.x * ((dHzdx.x / kx4.x + mzx.x) - (dHxdz.x * rky + mxz.x));
        ey.y = ca4.y * ey.y + cb4.y * ((dHzdx.y / kx4.y + mzx.y) - (dHxdz.y * rky + mxz.y));
        ey.z = ca4.z * ey.z + cb4.z * ((dHzdx.z / kx4.z + mzx.z) - (dHxdz.z * rky + mxz.z));
        ey.w = ca4.w * ey.w + cb4.w * ((dHzdx.w / kx4.w + mzx.w) - (dHxdz.w * rky + mxz.w));

        st4(outEy   + base, ey);
        st4(outmHzx + base, mzx);
        st4(outmHxz + base, mxz);
    }
}

// ------------- Kernel 2: update_H (x4 vector, both batches per thread) -------------
__global__ void __launch_bounds__(256) upd_H(
    const float* __restrict__ cq,
    const float* __restrict__ EyNew,
    const float* __restrict__ Hx, const float* __restrict__ Hz,
    const float* __restrict__ mEyx, const float* __restrict__ mEyz,
    const float* __restrict__ kyh, const float* __restrict__ ayh,
    const float* __restrict__ byh,
    const float* __restrict__ kxh, const float* __restrict__ axh,
    const float* __restrict__ bxh,
    const float* __restrict__ prdy, const float* __restrict__ prdx,
    float* __restrict__ outHx, float* __restrict__ outHz,
    float* __restrict__ outmEyx, float* __restrict__ outmEyz,
    int NY, int NX)
{
    int x4 = (blockIdx.x * blockDim.x + threadIdx.x) * 4;
    int y  = blockIdx.y * blockDim.y + threadIdx.y;
    if (x4 >= NX || y >= NY) return;

    const float rdx = *prdx;
    const float rdy = *prdy;

    size_t plane = (size_t)NY * NX;
    size_t cell  = (size_t)y * NX + x4;

    const bool xlo = (x4 >= 4);
    const bool xhi = (x4 + 4 < NX);
    const bool ym1 = (y >= 1), yp1 = (y + 1 < NY), yp2 = (y + 2 < NY);

    // ---- coefficients: loaded ONCE, used for both batches ----
    float4 bxh4 = ld4(bxh + x4);
    float4 axh4 = ld4(axh + x4);
    float4 kxh4 = ld4(kxh + x4);
    float  byhv = byh[y], ayhv = ayh[y];
    float  rkyh = 1.0f / kyh[y];
    float4 cq4  = ld4(cq + cell);

    #pragma unroll
    for (int b = 0; b < NB; b++) {
        size_t base = (size_t)b * plane + cell;

        // x-derivative of new Ey
        float4 c = ld4(EyNew + base);
        float4 p = xlo ? ld4(EyNew + base - 4) : f4zero();
        float4 n = xhi ? ld4(EyNew + base + 4) : f4zero();
        float4 dEydx = xderiv_H(c, p, n, rdx);

        // y-derivative of new Ey
        float4 rm1 = ym1 ? ld4(EyNew + base -   (size_t)NX) : f4zero();
        float4 rp1 = yp1 ? ld4(EyNew + base +   (size_t)NX) : f4zero();
        float4 rp2 = yp2 ? ld4(EyNew + base + 2*(size_t)NX) : f4zero();
        float4 dEydz = stencil4(rp1, c, rp2, rm1, rdy);

        float4 mez = ld4(mEyz + base);
        mez.x = byhv * mez.x + ayhv * dEydz.x;
        mez.y = byhv * mez.y + ayhv * dEydz.y;
        mez.z = byhv * mez.z + ayhv * dEydz.z;
        mez.w = byhv * mez.w + ayhv * dEydz.w;

        float4 mex = ld4(mEyx + base);
        mex.x = bxh4.x * mex.x + axh4.x * dEydx.x;
        mex.y = bxh4.y * mex.y + axh4.y * dEydx.y;
        mex.z = bxh4.z * mex.z + axh4.z * dEydx.z;
        mex.w = bxh4.w * mex.w + axh4.w * dEydx.w;

        float4 hx = ld4(Hx + base);
        hx.x = hx.x - cq4.x * (dEydz.x * rkyh + mez.x);
        hx.y = hx.y - cq4.y * (dEydz.y * rkyh + mez.y);
        hx.z = hx.z - cq4.z * (dEydz.z * rkyh + mez.z);
        hx.w = hx.w - cq4.w * (dEydz.w * rkyh + mez.w);

        float4 hz = ld4(Hz + base);
        hz.x = hz.x + cq4.x * (dEydx.x / kxh4.x + mex.x);
        hz.y = hz.y + cq4.y * (dEydx.y / kxh4.y + mex.y);
        hz.z = hz.z + cq4.z * (dEydx.z / kxh4.z + mex.z);
        hz.w = hz.w + cq4.w * (dEydx.w / kxh4.w + mex.w);

        st4(outHx   + base, hx);
        st4(outHz   + base, hz);
        st4(outmEyz + base, mez);
        st4(outmEyx + base, mex);
    }
}

extern "C" void kernel_launch(void* const* d_in, const int* in_sizes, int n_in,
                              void* d_out, int out_size)
{
    const float* ca    = (const float*)d_in[0];
    const float* cb    = (const float*)d_in[1];
    const float* cq    = (const float*)d_in[2];
    const float* Ey    = (const float*)d_in[3];
    const float* Hx    = (const float*)d_in[4];
    const float* Hz    = (const float*)d_in[5];
    const float* mHxz  = (const float*)d_in[6];
    const float* mHzx  = (const float*)d_in[7];
    const float* mEyx  = (const float*)d_in[8];
    const float* mEyz  = (const float*)d_in[9];
    const float* ky    = (const float*)d_in[10];
    const float* kyh   = (const float*)d_in[11];
    const float* ay    = (const float*)d_in[12];
    const float* ayh   = (const float*)d_in[13];
    const float* by    = (const float*)d_in[14];
    const float* byh   = (const float*)d_in[15];
    const float* kx    = (const float*)d_in[16];
    const float* kxh   = (const float*)d_in[17];
    const float* ax    = (const float*)d_in[18];
    const float* axh   = (const float*)d_in[19];
    const float* bx    = (const float*)d_in[20];
    const float* bxh   = (const float*)d_in[21];
    const float* prdy  = (const float*)d_in[22];
    const float* prdx  = (const float*)d_in[23];

    int NY = in_sizes[10];
    int NX = in_sizes[16];
    // NB==2 batches handled inside each thread (B is 2 for this problem)

    size_t plane = (size_t)NY * NX;
    size_t field = (size_t)NB * plane;

    float* out = (float*)d_out;
    float* oEy   = out + 0 * field;
    float* oHx   = out + 1 * field;
    float* oHz   = out + 2 * field;
    float* omHxz = out + 3 * field;
    float* omHzx = out + 4 * field;
    float* omEyx = out + 5 * field;
    float* omEyz = out + 6 * field;

    // each thread: 4 x-elements, both batches
    dim3 block(64, 4, 1);
    int nx4 = NX / 4;                       // 512
    dim3 grid((nx4 + 63) / 64, (NY + 3) / 4, 1);

    upd_E<<<grid, block>>>(ca, cb, Ey, Hx, Hz, mHxz, mHzx,
                           ky, ay, by, kx, ax, bx, prdy, prdx,
                           oEy, omHxz, omHzx, NY, NX);

    upd_H<<<grid, block>>>(cq, oEy, Hx, Hz, mEyx, mEyz,
                           kyh, ayh, byh, kxh, axh, bxh, prdy, prdx,
                           oHx, oHz, omEyx, omEyz, NY, NX);
}